// round 9
// baseline (speedup 1.0000x reference)
#include <cuda_runtime.h>

#define IH 1024
#define IW 1024
#define TJ 15              // owned cell rows/cols per block (15x15 cells = 30x30 px)
#define BDIM 17            // halo 2x2-block rows/cols in smem (17x17)
#define IMGS_PER_BLOCK 8

__device__ __forceinline__ float tanhf_fast(float x) {
    float y; asm("tanh.approx.f32 %0, %1;" : "=f"(y) : "f"(x)); return y;
}

__global__ __launch_bounds__(256, 5)
void ae_kernel(const float* __restrict__ img,
               const float* __restrict__ w_conv,  // (2,1,2,2)
               const float* __restrict__ b_conv,  // (2,)
               const float* __restrict__ W_b,     // (2,2)
               const float* __restrict__ b_b,     // (2,)
               const float* __restrict__ W_d,     // (2,1,2,2)
               const float* __restrict__ b_d,     // (1,)
               float* __restrict__ out)
{
    // double-buffered input halo (disjoint 2x2 pixel blocks) and top-group stage
    __shared__ float4 s_blk[2][BDIM * BDIM];   // 2 x 4.6 KB
    __shared__ float4 s_top[2][256];           // 2 x 4 KB

    const int tid = threadIdx.x;
    const int a  = tid >> 4;      // patch/cell row 0..15
    const int cb = tid & 15;      // patch/cell col 0..15
    const int bk = blockIdx.x, bj = blockIdx.y, bz = blockIdx.z;

    const int j0 = bj * TJ;
    const int k0 = bk * TJ;
    const int rbase = 2 * j0 - 2;   // pixel row of block row 0
    const int cbase = 2 * k0 - 2;

    // ---- tiny weights -> registers (uniform, hoisted across all images) ----
    const float4 wc0 = __ldg((const float4*)w_conv);
    const float4 wc1 = __ldg((const float4*)(w_conv + 4));
    const float2 bc  = __ldg((const float2*)b_conv);
    const float4 wb  = __ldg((const float4*)W_b);
    const float2 bb  = __ldg((const float2*)b_b);
    float wd0h[4], wd1h[4];
    {
        const float4 t0 = __ldg((const float4*)W_d);
        const float4 t1 = __ldg((const float4*)(W_d + 4));
        wd0h[0] = t0.x * 0.5f; wd0h[1] = t0.y * 0.5f; wd0h[2] = t0.z * 0.5f; wd0h[3] = t0.w * 0.5f;
        wd1h[0] = t1.x * 0.5f; wd1h[1] = t1.y * 0.5f; wd1h[2] = t1.z * 0.5f; wd1h[3] = t1.w * 0.5f;
    }
    const float bdh = __ldg(b_d) * 0.5f;
    const float thc = tanhf_fast(bdh);      // tanh for inactive quadrants (uniform)

    // ---- per-thread constants (hoisted) ----
    const int jr = j0 + a - 1;              // this thread's patch row
    const int kc = k0 + cb - 1;             // this thread's patch col
    const float hf = ((unsigned)jr <= 510u && (unsigned)kc <= 510u) ? 0.5f : 0.0f;
    const float hfc = fmaf(thc, hf, hf);    // constant quadrant value, pre-scaled

    const int h = 2 * (j0 + a);
    const int w = 2 * (k0 + cb);
    const bool cell_ok = (a < 15) & (cb < 15) & (h < IH) & (w < IW);
    const bool vj1 = (unsigned)jr        <= 510u;
    const bool vj2 = (unsigned)(jr + 1)  <= 510u;
    const bool vk  = (unsigned)kc        <= 510u;
    const bool vkn = (unsigned)(kc + 1)  <= 510u;
    const int cnt = ((int)vj1 + (int)vj2) * ((int)vk + (int)vkn);
    const float rcp = (cnt == 4) ? 0.25f : ((cnt == 2) ? 0.5f : 1.0f);

    const int sbase = a * BDIM + cb;

    // ---- staging addressing for element 0 (image-invariant, hoisted) ----
    const int R0 = tid / BDIM, C0 = tid - R0 * BDIM;
    const int gr0 = rbase + 2 * R0, gc0 = cbase + 2 * C0;
    const bool cok0  = (unsigned)gc0 < 1024u;
    const bool rtop0 = (unsigned)gr0 < 1024u;
    const bool rbot0 = (unsigned)(gr0 + 1) < 1024u;
    const int o0 = gr0 * IW + gc0;

    const float* imgb = img + (size_t)(IMGS_PER_BLOCK * bz) * (IH * IW);
    float* op = out + (size_t)(IMGS_PER_BLOCK * bz) * (IH * IW)
                    + (size_t)h * IW + w;

    // element-1 addressing recomputed per use (only 33 threads; warps 2-7 skip)
#define STAGE(buf, base_ptr) do {                                          \
        float2 top_ = make_float2(0.0f, 0.0f);                             \
        float2 bot_ = make_float2(0.0f, 0.0f);                             \
        if (cok0) {                                                        \
            const float* p_ = (base_ptr) + o0;                             \
            if (rtop0) top_ = *(const float2*)(p_);                        \
            if (rbot0) bot_ = *(const float2*)(p_ + IW);                   \
        }                                                                  \
        s_blk[buf][tid] = make_float4(top_.x, top_.y, bot_.x, bot_.y);     \
        if (tid < (BDIM * BDIM - 256)) {                                   \
            const int t1_ = tid + 256;                                     \
            const int R1_ = t1_ / BDIM, C1_ = t1_ - R1_ * BDIM;            \
            const int gr1_ = rbase + 2 * R1_, gc1_ = cbase + 2 * C1_;      \
            float2 t2_ = make_float2(0.0f, 0.0f);                          \
            float2 b2_ = make_float2(0.0f, 0.0f);                          \
            if ((unsigned)gc1_ < 1024u) {                                  \
                const float* p_ = (base_ptr) + (gr1_ * IW + gc1_);         \
                if ((unsigned)gr1_ < 1024u)       t2_ = *(const float2*)(p_);       \
                if ((unsigned)(gr1_ + 1) < 1024u) b2_ = *(const float2*)(p_ + IW);  \
            }                                                              \
            s_blk[buf][t1_] = make_float4(t2_.x, t2_.y, b2_.x, b2_.y);     \
        }                                                                  \
    } while (0)

    // ---- prologue: stage image 0 ----
    STAGE(0, imgb);
    __syncthreads();

#pragma unroll 1
    for (int ib = 0; ib < IMGS_PER_BLOCK; ib++) {
        const int p = ib & 1;

        // ---- stage next image into the other buffer (overlaps with compute) ----
        if (ib < IMGS_PER_BLOCK - 1) {
            STAGE(1 - p, imgb + (ib + 1) * (IH * IW));
        }

        // ---- compute this thread's single patch from blk[p] ----
        const float4 A  = s_blk[p][sbase];
        const float4 Bq = s_blk[p][sbase + 1];
        const float4 C  = s_blk[p][sbase + BDIM];
        const float4 D  = s_blk[p][sbase + BDIM + 1];

        // conv(2ch) -> relu
        float cv0[4], cv1[4];
#define CONVB(e, B) do { \
        float v0 = fmaf(wc0.x, (B).x, fmaf(wc0.y, (B).y, fmaf(wc0.z, (B).z, fmaf(wc0.w, (B).w, bc.x)))); \
        float v1 = fmaf(wc1.x, (B).x, fmaf(wc1.y, (B).y, fmaf(wc1.z, (B).z, fmaf(wc1.w, (B).w, bc.y)))); \
        cv0[e] = fmaxf(v0, 0.0f); cv1[e] = fmaxf(v1, 0.0f); } while (0)
        CONVB(0, A); CONVB(1, Bq); CONVB(2, C); CONVB(3, D);
#undef CONVB

        // argmax (first-max semantics: strict >)
        int am0 = 0, am1 = 0;
        float mv0 = cv0[0], mv1 = cv1[0];
#pragma unroll
        for (int e = 1; e < 4; e++) {
            if (cv0[e] > mv0) { mv0 = cv0[e]; am0 = e; }
            if (cv1[e] > mv1) { mv1 = cv1[e]; am1 = e; }
        }

        // dense + relu
        const float z0 = fmaxf(fmaf(mv0, wb.x, fmaf(mv1, wb.y, bb.x)), 0.0f);
        const float z1 = fmaxf(fmaf(mv0, wb.z, fmaf(mv1, wb.w, bb.y)), 0.0f);
        const float zz1 = (am0 == am1) ? z1 : 0.0f;

        // 8 live tanh, pre-scaled by hf: value = hf*(tanh+1)
        float th0s[4], th1s[4];
#pragma unroll
        for (int pq = 0; pq < 4; pq++) {
            th0s[pq] = fmaf(tanhf_fast(fmaf(z0, wd0h[pq], fmaf(zz1, wd1h[pq], bdh))), hf, hf);
            th1s[pq] = fmaf(tanhf_fast(fmaf(z1, wd1h[pq], bdh)), hf, hf);
        }

        // build quadrant groups via pure selects
        float4 grp[4];
#pragma unroll
        for (int g = 0; g < 4; g++) {
            const bool p0 = (am0 == g);
            const bool p1 = (am1 == g);
            grp[g].x = p0 ? th0s[0] : (p1 ? th1s[0] : hfc);
            grp[g].y = p0 ? th0s[1] : (p1 ? th1s[1] : hfc);
            grp[g].z = p0 ? th0s[2] : (p1 ? th1s[2] : hfc);
            grp[g].w = p0 ? th0s[3] : (p1 ? th1s[3] : hfc);
        }
        const float4 gTL = grp[0];   // -> above-left cell (combined via shfl+smem)
        const float4 gTR = grp[1];   // -> above cell
        const float4 gBL = grp[2];   // -> left cell (shfl)
        const float4 gBR = grp[3];   // -> own cell (regs)

        // combine TR with right-neighbor's TL, store ONE float4
        float4 sumT;
        sumT.x = gTR.x + __shfl_down_sync(0xffffffffu, gTL.x, 1);
        sumT.y = gTR.y + __shfl_down_sync(0xffffffffu, gTL.y, 1);
        sumT.z = gTR.z + __shfl_down_sync(0xffffffffu, gTL.z, 1);
        sumT.w = gTR.w + __shfl_down_sync(0xffffffffu, gTL.w, 1);
        s_top[p][tid] = sumT;

        // BL of right-neighbor patch
        float4 nBL;
        nBL.x = __shfl_down_sync(0xffffffffu, gBL.x, 1);
        nBL.y = __shfl_down_sync(0xffffffffu, gBL.y, 1);
        nBL.z = __shfl_down_sync(0xffffffffu, gBL.z, 1);
        nBL.w = __shfl_down_sync(0xffffffffu, gBL.w, 1);

        __syncthreads();   // single barrier: top[p] ready AND blk[1-p] staged

        // ---- gather + store ----
        if (cell_ok) {
            const float4 vT = s_top[p][tid + 16];   // (TR of patch below) + (TL of below-right)
            const float pix00 = (gBR.x + nBL.x) + vT.x;
            const float pix01 = (gBR.y + nBL.y) + vT.y;
            const float pix10 = (gBR.z + nBL.z) + vT.z;
            const float pix11 = (gBR.w + nBL.w) + vT.w;

            *(float2*)(op)      = make_float2(pix00 * rcp, pix01 * rcp);
            *(float2*)(op + IW) = make_float2(pix10 * rcp, pix11 * rcp);
        }
        op += IH * IW;
    }
#undef STAGE
}

extern "C" void kernel_launch(void* const* d_in, const int* in_sizes, int n_in,
                              void* d_out, int out_size) {
    const float* img    = (const float*)d_in[0];
    const float* w_conv = (const float*)d_in[1];
    const float* b_conv = (const float*)d_in[2];
    const float* W_b    = (const float*)d_in[3];
    const float* b_b    = (const float*)d_in[4];
    const float* W_d    = (const float*)d_in[5];
    const float* b_d    = (const float*)d_in[6];
    float* out = (float*)d_out;

    dim3 grid(35, 35, 1);   // 8 images per block
    dim3 block(256);
    ae_kernel<<<grid, block>>>(img, w_conv, b_conv, W_b, b_b, W_d, b_d, out);
}

// round 10
// speedup vs baseline: 1.0849x; 1.0849x over previous
#include <cuda_runtime.h>

#define IH 1024
#define IW 1024
#define TJ 15              // owned cell rows/cols per block (15x15 cells = 30x30 px)
#define BDIM 17            // halo 2x2-block rows/cols in smem (17x17)
#define IMGS_PER_BLOCK 8
#define IMG_PIX (IH * IW)

__device__ __forceinline__ float tanhf_fast(float x) {
    float y; asm("tanh.approx.f32 %0, %1;" : "=f"(y) : "f"(x)); return y;
}

__global__ __launch_bounds__(256, 4)
void ae_kernel(const float* __restrict__ img,
               const float* __restrict__ w_conv,  // (2,1,2,2)
               const float* __restrict__ b_conv,  // (2,)
               const float* __restrict__ W_b,     // (2,2)
               const float* __restrict__ b_b,     // (2,)
               const float* __restrict__ W_d,     // (2,1,2,2)
               const float* __restrict__ b_d,     // (1,)
               float* __restrict__ out)
{
    // double-buffered input halo (disjoint 2x2 pixel blocks) and top-group stage
    __shared__ float4 s_blk[2][BDIM * BDIM];   // 2 x 4.6 KB
    __shared__ float4 s_top[2][256];           // 2 x 4 KB

    const int tid = threadIdx.x;
    const int a  = tid >> 4;      // patch/cell row 0..15
    const int cb = tid & 15;      // patch/cell col 0..15
    const int bk = blockIdx.x, bj = blockIdx.y;

    const int j0 = bj * TJ;
    const int k0 = bk * TJ;
    const int rbase = 2 * j0 - 2;   // pixel row of block row 0
    const int cbase = 2 * k0 - 2;

    // ---- tiny weights -> registers (uniform, hoisted across all images) ----
    const float4 wc0 = __ldg((const float4*)w_conv);
    const float4 wc1 = __ldg((const float4*)(w_conv + 4));
    const float2 bc  = __ldg((const float2*)b_conv);
    const float4 wb  = __ldg((const float4*)W_b);
    const float2 bb  = __ldg((const float2*)b_b);
    float wd0h[4], wd1h[4];
    {
        const float4 t0 = __ldg((const float4*)W_d);
        const float4 t1 = __ldg((const float4*)(W_d + 4));
        wd0h[0] = t0.x * 0.5f; wd0h[1] = t0.y * 0.5f; wd0h[2] = t0.z * 0.5f; wd0h[3] = t0.w * 0.5f;
        wd1h[0] = t1.x * 0.5f; wd1h[1] = t1.y * 0.5f; wd1h[2] = t1.z * 0.5f; wd1h[3] = t1.w * 0.5f;
    }
    const float bdh = __ldg(b_d) * 0.5f;
    const float thc = tanhf_fast(bdh);      // tanh for inactive quadrants (uniform)

    // ---- per-thread constants (hoisted) ----
    const int jr = j0 + a - 1;              // this thread's patch row
    const int kc = k0 + cb - 1;             // this thread's patch col
    const float hf = ((unsigned)jr <= 510u && (unsigned)kc <= 510u) ? 0.5f : 0.0f;
    const float hfc = fmaf(thc, hf, hf);    // constant quadrant value, pre-scaled

    const int h = 2 * (j0 + a);
    const int w = 2 * (k0 + cb);
    const bool cell_ok = (a < 15) & (cb < 15) & (h < IH) & (w < IW);
    const bool vj1 = (unsigned)jr        <= 510u;
    const bool vj2 = (unsigned)(jr + 1)  <= 510u;
    const bool vk  = (unsigned)kc        <= 510u;
    const bool vkn = (unsigned)(kc + 1)  <= 510u;
    const int cnt = ((int)vj1 + (int)vj2) * ((int)vk + (int)vkn);
    const float rcp = (cnt == 4) ? 0.25f : ((cnt == 2) ? 0.5f : 1.0f);

    const int sbase = a * BDIM + cb;

    // ---- staging addressing (image-invariant, fully hoisted — R8 style) ----
    const int R0 = tid / BDIM, C0 = tid - R0 * BDIM;
    const int gr0 = rbase + 2 * R0, gc0 = cbase + 2 * C0;
    const bool cok0  = (unsigned)gc0 < 1024u;
    const bool rtop0 = (unsigned)gr0 < 1024u;
    const bool rbot0 = (unsigned)(gr0 + 1) < 1024u;
    const int o0 = gr0 * IW + gc0;

    const bool act1 = tid < (BDIM * BDIM - 256);      // 33 threads
    const int t1 = tid + 256;
    const int R1 = t1 / BDIM, C1 = t1 - R1 * BDIM;
    const int gr1 = rbase + 2 * R1, gc1 = cbase + 2 * C1;
    const bool cok1  = act1 && ((unsigned)gc1 < 1024u);
    const bool rtop1 = (unsigned)gr1 < 1024u;
    const bool rbot1 = (unsigned)(gr1 + 1) < 1024u;
    const int o1 = gr1 * IW + gc1;

    const float* nextimg = img;                        // image to stage next
    float* op = out + (size_t)h * IW + w;

#define STAGE(buf, base_ptr) do {                                          \
        float2 top_ = make_float2(0.0f, 0.0f);                             \
        float2 bot_ = make_float2(0.0f, 0.0f);                             \
        if (cok0) {                                                        \
            const float* p_ = (base_ptr) + o0;                             \
            if (rtop0) top_ = *(const float2*)(p_);                        \
            if (rbot0) bot_ = *(const float2*)(p_ + IW);                   \
        }                                                                  \
        s_blk[buf][tid] = make_float4(top_.x, top_.y, bot_.x, bot_.y);     \
        if (act1) {                                                        \
            float2 t2_ = make_float2(0.0f, 0.0f);                         \
            float2 b2_ = make_float2(0.0f, 0.0f);                         \
            if (cok1) {                                                    \
                const float* p_ = (base_ptr) + o1;                         \
                if (rtop1) t2_ = *(const float2*)(p_);                     \
                if (rbot1) b2_ = *(const float2*)(p_ + IW);                \
            }                                                              \
            s_blk[buf][t1] = make_float4(t2_.x, t2_.y, b2_.x, b2_.y);      \
        }                                                                  \
    } while (0)

    // ---- prologue: stage image 0 ----
    STAGE(0, nextimg);
    nextimg += IMG_PIX;
    __syncthreads();

#pragma unroll 2
    for (int ib = 0; ib < IMGS_PER_BLOCK; ib++) {
        const int p = ib & 1;    // compile-time within each unrolled copy

        // ---- stage next image into the other buffer (overlaps with compute) ----
        if (ib < IMGS_PER_BLOCK - 1) {
            STAGE(1 - p, nextimg);
        }
        nextimg += IMG_PIX;

        // ---- compute this thread's single patch from blk[p] ----
        const float4 A  = s_blk[p][sbase];
        const float4 Bq = s_blk[p][sbase + 1];
        const float4 C  = s_blk[p][sbase + BDIM];
        const float4 D  = s_blk[p][sbase + BDIM + 1];

        // conv(2ch) -> relu
        float cv0[4], cv1[4];
#define CONVB(e, B) do { \
        float v0 = fmaf(wc0.x, (B).x, fmaf(wc0.y, (B).y, fmaf(wc0.z, (B).z, fmaf(wc0.w, (B).w, bc.x)))); \
        float v1 = fmaf(wc1.x, (B).x, fmaf(wc1.y, (B).y, fmaf(wc1.z, (B).z, fmaf(wc1.w, (B).w, bc.y)))); \
        cv0[e] = fmaxf(v0, 0.0f); cv1[e] = fmaxf(v1, 0.0f); } while (0)
        CONVB(0, A); CONVB(1, Bq); CONVB(2, C); CONVB(3, D);
#undef CONVB

        // argmax (first-max semantics: strict >)
        int am0 = 0, am1 = 0;
        float mv0 = cv0[0], mv1 = cv1[0];
#pragma unroll
        for (int e = 1; e < 4; e++) {
            if (cv0[e] > mv0) { mv0 = cv0[e]; am0 = e; }
            if (cv1[e] > mv1) { mv1 = cv1[e]; am1 = e; }
        }

        // dense + relu
        const float z0 = fmaxf(fmaf(mv0, wb.x, fmaf(mv1, wb.y, bb.x)), 0.0f);
        const float z1 = fmaxf(fmaf(mv0, wb.z, fmaf(mv1, wb.w, bb.y)), 0.0f);
        const float zz1 = (am0 == am1) ? z1 : 0.0f;

        // 8 live tanh, pre-scaled by hf: value = hf*(tanh+1)
        float th0s[4], th1s[4];
#pragma unroll
        for (int pq = 0; pq < 4; pq++) {
            th0s[pq] = fmaf(tanhf_fast(fmaf(z0, wd0h[pq], fmaf(zz1, wd1h[pq], bdh))), hf, hf);
            th1s[pq] = fmaf(tanhf_fast(fmaf(z1, wd1h[pq], bdh)), hf, hf);
        }

        // build quadrant groups via pure selects
        float4 grp[4];
#pragma unroll
        for (int g = 0; g < 4; g++) {
            const bool p0 = (am0 == g);
            const bool p1 = (am1 == g);
            grp[g].x = p0 ? th0s[0] : (p1 ? th1s[0] : hfc);
            grp[g].y = p0 ? th0s[1] : (p1 ? th1s[1] : hfc);
            grp[g].z = p0 ? th0s[2] : (p1 ? th1s[2] : hfc);
            grp[g].w = p0 ? th0s[3] : (p1 ? th1s[3] : hfc);
        }
        const float4 gTL = grp[0];   // -> above-left cell (combined via shfl+smem)
        const float4 gTR = grp[1];   // -> above cell
        const float4 gBL = grp[2];   // -> left cell (shfl)
        const float4 gBR = grp[3];   // -> own cell (regs)

        // combine TR with right-neighbor's TL, store ONE float4
        float4 sumT;
        sumT.x = gTR.x + __shfl_down_sync(0xffffffffu, gTL.x, 1);
        sumT.y = gTR.y + __shfl_down_sync(0xffffffffu, gTL.y, 1);
        sumT.z = gTR.z + __shfl_down_sync(0xffffffffu, gTL.z, 1);
        sumT.w = gTR.w + __shfl_down_sync(0xffffffffu, gTL.w, 1);
        s_top[p][tid] = sumT;

        // BL of right-neighbor patch
        float4 nBL;
        nBL.x = __shfl_down_sync(0xffffffffu, gBL.x, 1);
        nBL.y = __shfl_down_sync(0xffffffffu, gBL.y, 1);
        nBL.z = __shfl_down_sync(0xffffffffu, gBL.z, 1);
        nBL.w = __shfl_down_sync(0xffffffffu, gBL.w, 1);

        __syncthreads();   // single barrier: top[p] ready AND blk[1-p] staged

        // ---- gather + store ----
        if (cell_ok) {
            const float4 vT = s_top[p][tid + 16];   // (TR of patch below) + (TL of below-right)
            const float pix00 = (gBR.x + nBL.x) + vT.x;
            const float pix01 = (gBR.y + nBL.y) + vT.y;
            const float pix10 = (gBR.z + nBL.z) + vT.z;
            const float pix11 = (gBR.w + nBL.w) + vT.w;

            *(float2*)(op)      = make_float2(pix00 * rcp, pix01 * rcp);
            *(float2*)(op + IW) = make_float2(pix10 * rcp, pix11 * rcp);
        }
        op += IMG_PIX;
    }
#undef STAGE
}

extern "C" void kernel_launch(void* const* d_in, const int* in_sizes, int n_in,
                              void* d_out, int out_size) {
    const float* img    = (const float*)d_in[0];
    const float* w_conv = (const float*)d_in[1];
    const float* b_conv = (const float*)d_in[2];
    const float* W_b    = (const float*)d_in[3];
    const float* b_b    = (const float*)d_in[4];
    const float* W_d    = (const float*)d_in[5];
    const float* b_d    = (const float*)d_in[6];
    float* out = (float*)d_out;

    dim3 grid(35, 35, 1);   // 8 images per block
    dim3 block(256);
    ae_kernel<<<grid, block>>>(img, w_conv, b_conv, W_b, b_b, W_d, b_d, out);
}

// round 11
// speedup vs baseline: 1.2655x; 1.1664x over previous
#include <cuda_runtime.h>

#define IH 1024
#define IW 1024
#define IMG_PIX (IH * IW)
#define NSEG 32            // row segments per image (16 cell rows each)
#define SEG_ROWS 16
#define COLW 17            // col-warps per row strip (31 owned cell cols each)
#define WPB 8              // warps per block

__device__ __forceinline__ float tanhf_fast(float x) {
    float y; asm("tanh.approx.f32 %0, %1;" : "=f"(y) : "f"(x)); return y;
}

__global__ __launch_bounds__(256, 3)
void ae_kernel(const float* __restrict__ img,
               const float* __restrict__ w_conv,  // (2,1,2,2)
               const float* __restrict__ b_conv,  // (2,)
               const float* __restrict__ W_b,     // (2,2)
               const float* __restrict__ b_b,     // (2,)
               const float* __restrict__ W_d,     // (2,1,2,2)
               const float* __restrict__ b_d,     // (1,)
               float* __restrict__ out)
{
    const int lane = threadIdx.x & 31;
    const int gw   = blockIdx.x * WPB + (threadIdx.x >> 5);
    const int c    = gw % COLW;          // col-warp
    const int t    = gw / COLW;
    const int s    = t & (NSEG - 1);     // row segment
    const int im   = t >> 5;             // image

    // ---- tiny weights -> registers (uniform) ----
    const float4 wc0 = __ldg((const float4*)w_conv);
    const float4 wc1 = __ldg((const float4*)(w_conv + 4));
    const float2 bc  = __ldg((const float2*)b_conv);
    const float4 wb  = __ldg((const float4*)W_b);
    const float2 bb  = __ldg((const float2*)b_b);
    float wd0h[4], wd1h[4];
    {
        const float4 t0 = __ldg((const float4*)W_d);
        const float4 t1 = __ldg((const float4*)(W_d + 4));
        wd0h[0]=t0.x*0.5f; wd0h[1]=t0.y*0.5f; wd0h[2]=t0.z*0.5f; wd0h[3]=t0.w*0.5f;
        wd1h[0]=t1.x*0.5f; wd1h[1]=t1.y*0.5f; wd1h[2]=t1.z*0.5f; wd1h[3]=t1.w*0.5f;
    }
    const float bdh = __ldg(b_d) * 0.5f;
    const float thc = tanhf_fast(bdh);

    // ---- lane geometry (invariant) ----
    const int kc = 31 * c + lane - 1;     // own patch col (may be -1 or >510)
    const int CB = kc + 1;                // own cell col
    const float hfk = ((unsigned)kc <= 510u) ? 0.5f : 0.0f;
    const int colf = (int)((unsigned)kc <= 510u) + (int)((unsigned)CB <= 510u);
    const float rcp_mid  = (colf == 2) ? 0.25f : 0.5f;   // interior cell rows
    const float rcp_edge = (colf == 2) ? 0.5f  : 1.0f;   // cell rows 0 and 511
    const bool cell_ok = (lane < 31) && (CB <= 511);

    const int gcL = 2 * kc;
    const bool okL = (unsigned)gcL < 1024u;
    const bool okR = (unsigned)(gcL + 2) < 1024u;

    const float* ib = img + (size_t)im * IMG_PIX;
    float* op = out + (size_t)im * IMG_PIX + (size_t)(32 * s) * IW + 2 * CB;

    // load block row b (pixel rows 2b, 2b+1; own cols [2kc,2kc+2), right [2kc+2,2kc+4))
    auto LOADBR = [&](int b, float4& O, float4& R) {
        const float* p = ib + (long long)(2 * b) * IW + gcL;
        float2 ot = make_float2(0.f, 0.f), obm = ot, rt = ot, rb = ot;
        if ((unsigned)(2 * b) < 1024u)     { if (okL) ot  = *(const float2*)p;          if (okR) rt = *(const float2*)(p + 2); }
        if ((unsigned)(2 * b + 1) < 1024u) { if (okL) obm = *(const float2*)(p + IW);   if (okR) rb = *(const float2*)(p + IW + 2); }
        O = make_float4(ot.x, ot.y, obm.x, obm.y);
        R = make_float4(rt.x, rt.y, rb.x, rb.y);
    };

    // 2-deep block-row window: Ow[b&1] holds block row b for b in {pr, pr+1}
    float4 Ow[2], Rw[2];
    const int pr0 = 16 * s - 1;           // first (warm-up) patch row; always odd
    LOADBR(pr0,     Ow[1], Rw[1]);
    LOADBR(pr0 + 1, Ow[0], Rw[0]);
    float4 carry = make_float4(0.f, 0.f, 0.f, 0.f);   // BR(own)+BL(right) of prev patch row

#pragma unroll 2
    for (int i = 0; i <= SEG_ROWS; i++) {
        const int pr = pr0 + i;           // patch row this iteration
        const int lo = (i + 1) & 1;       // window slot of block row pr
        const int hi = i & 1;             // slot of block row pr+1

        // prefetch block row pr+2 (LOADBR bounds-checks rows; tail loads are zeros)
        float4 tO, tR;
        LOADBR(pr + 2, tO, tR);

        const float4 A  = Ow[lo];         // TL block of patch
        const float4 Bq = Rw[lo];         // TR
        const float4 C  = Ow[hi];         // BL
        const float4 D  = Rw[hi];         // BR

        // conv(2ch) -> relu
        float cv0[4], cv1[4];
#define CONVB(e, B) do { \
        float v0 = fmaf(wc0.x, (B).x, fmaf(wc0.y, (B).y, fmaf(wc0.z, (B).z, fmaf(wc0.w, (B).w, bc.x)))); \
        float v1 = fmaf(wc1.x, (B).x, fmaf(wc1.y, (B).y, fmaf(wc1.z, (B).z, fmaf(wc1.w, (B).w, bc.y)))); \
        cv0[e] = fmaxf(v0, 0.0f); cv1[e] = fmaxf(v1, 0.0f); } while (0)
        CONVB(0, A); CONVB(1, Bq); CONVB(2, C); CONVB(3, D);
#undef CONVB

        // argmax (first-max semantics: strict >)
        int am0 = 0, am1 = 0;
        float mv0 = cv0[0], mv1 = cv1[0];
#pragma unroll
        for (int e = 1; e < 4; e++) {
            if (cv0[e] > mv0) { mv0 = cv0[e]; am0 = e; }
            if (cv1[e] > mv1) { mv1 = cv1[e]; am1 = e; }
        }

        // dense + relu
        const float z0 = fmaxf(fmaf(mv0, wb.x, fmaf(mv1, wb.y, bb.x)), 0.0f);
        const float z1 = fmaxf(fmaf(mv0, wb.z, fmaf(mv1, wb.w, bb.y)), 0.0f);
        const float zz1 = (am0 == am1) ? z1 : 0.0f;

        // row+col validity folded into scale
        const float hf = ((unsigned)pr <= 510u) ? hfk : 0.0f;
        const float hfc = fmaf(thc, hf, hf);

        // 8 live tanh, pre-scaled: value = hf*(tanh+1)
        float th0s[4], th1s[4];
#pragma unroll
        for (int pq = 0; pq < 4; pq++) {
            th0s[pq] = fmaf(tanhf_fast(fmaf(z0, wd0h[pq], fmaf(zz1, wd1h[pq], bdh))), hf, hf);
            th1s[pq] = fmaf(tanhf_fast(fmaf(z1, wd1h[pq], bdh)), hf, hf);
        }

        // quadrant groups via selects
        float4 grp[4];
#pragma unroll
        for (int g = 0; g < 4; g++) {
            const bool p0 = (am0 == g);
            const bool p1 = (am1 == g);
            grp[g].x = p0 ? th0s[0] : (p1 ? th1s[0] : hfc);
            grp[g].y = p0 ? th0s[1] : (p1 ? th1s[1] : hfc);
            grp[g].z = p0 ? th0s[2] : (p1 ? th1s[2] : hfc);
            grp[g].w = p0 ? th0s[3] : (p1 ? th1s[3] : hfc);
        }
        const float4 gTL = grp[0];
        const float4 gTR = grp[1];
        const float4 gBL = grp[2];
        const float4 gBR = grp[3];

        // horizontal routing: right-neighbor lane's TL and BL
        float4 nTL, nBL;
        nTL.x = __shfl_down_sync(0xffffffffu, gTL.x, 1);
        nTL.y = __shfl_down_sync(0xffffffffu, gTL.y, 1);
        nTL.z = __shfl_down_sync(0xffffffffu, gTL.z, 1);
        nTL.w = __shfl_down_sync(0xffffffffu, gTL.w, 1);
        nBL.x = __shfl_down_sync(0xffffffffu, gBL.x, 1);
        nBL.y = __shfl_down_sync(0xffffffffu, gBL.y, 1);
        nBL.z = __shfl_down_sync(0xffffffffu, gBL.z, 1);
        nBL.w = __shfl_down_sync(0xffffffffu, gBL.w, 1);

        // emit cell row A = pr (skip warm-up i=0); vertical routing via 'carry'
        if (i > 0) {
            if (cell_ok) {
                const float rcp = (pr == 0 || pr == 511) ? rcp_edge : rcp_mid;
                const float pix00 = (carry.x + gTR.x) + nTL.x;
                const float pix01 = (carry.y + gTR.y) + nTL.y;
                const float pix10 = (carry.z + gTR.z) + nTL.z;
                const float pix11 = (carry.w + gTR.w) + nTL.w;
                *(float2*)(op)      = make_float2(pix00 * rcp, pix01 * rcp);
                *(float2*)(op + IW) = make_float2(pix10 * rcp, pix11 * rcp);
            }
            op += 2 * IW;
        }

        // new vertical carry for cell row pr+1
        carry.x = gBR.x + nBL.x;
        carry.y = gBR.y + nBL.y;
        carry.z = gBR.z + nBL.z;
        carry.w = gBR.w + nBL.w;

        // slide window: slot lo now holds block row pr+2
        Ow[lo] = tO;
        Rw[lo] = tR;
    }
}

extern "C" void kernel_launch(void* const* d_in, const int* in_sizes, int n_in,
                              void* d_out, int out_size) {
    const float* img    = (const float*)d_in[0];
    const float* w_conv = (const float*)d_in[1];
    const float* b_conv = (const float*)d_in[2];
    const float* W_b    = (const float*)d_in[3];
    const float* b_b    = (const float*)d_in[4];
    const float* W_d    = (const float*)d_in[5];
    const float* b_d    = (const float*)d_in[6];
    float* out = (float*)d_out;

    // 8 imgs x 32 segments x 17 col-warps = 4352 warps / 8 per block
    dim3 grid(8 * NSEG * COLW / WPB);   // 544 blocks
    dim3 block(256);
    ae_kernel<<<grid, block>>>(img, w_conv, b_conv, W_b, b_b, W_d, b_d, out);
}

// round 12
// speedup vs baseline: 1.4024x; 1.1082x over previous
#include <cuda_runtime.h>

#define IH 1024
#define IW 1024
#define IMG_PIX (IH * IW)
#define NSEG 32            // row segments per image (16 cell rows each)
#define SEG_ROWS 16
#define COLW 17            // col-warps per row strip (31 owned cell cols each)
#define WPB 4              // warps per block

__device__ __forceinline__ float tanhf_fast(float x) {
    float y; asm("tanh.approx.f32 %0, %1;" : "=f"(y) : "f"(x)); return y;
}

__global__ __launch_bounds__(128, 7)
void ae_kernel(const float* __restrict__ img,
               const float* __restrict__ w_conv,  // (2,1,2,2)
               const float* __restrict__ b_conv,  // (2,)
               const float* __restrict__ W_b,     // (2,2)
               const float* __restrict__ b_b,     // (2,)
               const float* __restrict__ W_d,     // (2,1,2,2)
               const float* __restrict__ b_d,     // (1,)
               float* __restrict__ out)
{
    const int lane = threadIdx.x & 31;
    const int gw   = blockIdx.x * WPB + (threadIdx.x >> 5);
    const int c    = gw % COLW;          // col-warp
    const int t    = gw / COLW;
    const int s    = t & (NSEG - 1);     // row segment
    const int im   = t >> 5;             // image

    // ---- tiny weights -> registers (uniform) ----
    const float4 wc0 = __ldg((const float4*)w_conv);
    const float4 wc1 = __ldg((const float4*)(w_conv + 4));
    const float2 bc  = __ldg((const float2*)b_conv);
    const float4 wb  = __ldg((const float4*)W_b);
    const float2 bb  = __ldg((const float2*)b_b);
    float wd0h[4], wd1h[4];
    {
        const float4 t0 = __ldg((const float4*)W_d);
        const float4 t1 = __ldg((const float4*)(W_d + 4));
        wd0h[0]=t0.x*0.5f; wd0h[1]=t0.y*0.5f; wd0h[2]=t0.z*0.5f; wd0h[3]=t0.w*0.5f;
        wd1h[0]=t1.x*0.5f; wd1h[1]=t1.y*0.5f; wd1h[2]=t1.z*0.5f; wd1h[3]=t1.w*0.5f;
    }
    const float bdh = __ldg(b_d) * 0.5f;
    const float thc = tanhf_fast(bdh);

    // ---- lane geometry (invariant) ----
    const int kc = 31 * c + lane - 1;     // own patch col (may be -1 or >510)
    const int CB = kc + 1;                // own cell col
    const float hfk = ((unsigned)kc <= 510u) ? 0.5f : 0.0f;
    const int colf = (int)((unsigned)kc <= 510u) + (int)((unsigned)CB <= 510u);
    const float rcp_mid  = (colf == 2) ? 0.25f : 0.5f;   // interior cell rows
    const float rcp_edge = (colf == 2) ? 0.5f  : 1.0f;   // cell rows 0 and 511
    const bool cell_ok = (lane < 31) && (CB <= 511);

    // clamped column bases (OOB patches have hf=0; clamped garbage never escapes)
    const int gcL = 2 * kc;
    const int colO = min(max(gcL, 0), 1022);       // own block cols
    const int colR = min(max(gcL + 2, 0), 1022);   // right block cols

    const float* ibase = img + (size_t)im * IMG_PIX;
    float* op = out + (size_t)im * IMG_PIX + (size_t)(32 * s) * IW + 2 * CB;

    // load block row b (pixel rows clamp(2b), +1), unconditional LDG.64 x4
    auto LOADBR = [&](int b, float4& O, float4& R) {
        const int ro = min(max(2 * b, 0), 1022);
        const float* p = ibase + (long long)ro * IW;
        const float2 ot  = *(const float2*)(p + colO);
        const float2 rt  = *(const float2*)(p + colR);
        const float2 obm = *(const float2*)(p + IW + colO);
        const float2 rb  = *(const float2*)(p + IW + colR);
        O = make_float4(ot.x, ot.y, obm.x, obm.y);
        R = make_float4(rt.x, rt.y, rb.x, rb.y);
    };

    // 2-deep block-row window: Ow[b&1] holds block row b for b in {pr, pr+1}
    float4 Ow[2], Rw[2];
    const int pr0 = 16 * s - 1;           // first (warm-up) patch row; always odd
    LOADBR(pr0,     Ow[1], Rw[1]);
    LOADBR(pr0 + 1, Ow[0], Rw[0]);
    float4 carry = make_float4(0.f, 0.f, 0.f, 0.f);   // BR(own)+BL(right) of prev patch row

#pragma unroll 2
    for (int i = 0; i <= SEG_ROWS; i++) {
        const int pr = pr0 + i;           // patch row this iteration
        const int lo = (i + 1) & 1;       // window slot of block row pr
        const int hi = i & 1;             // slot of block row pr+1

        // prefetch block row pr+2 (clamped; tail garbage is masked by hf=0)
        float4 tO, tR;
        LOADBR(pr + 2, tO, tR);

        const float4 A  = Ow[lo];         // TL block of patch
        const float4 Bq = Rw[lo];         // TR
        const float4 C  = Ow[hi];         // BL
        const float4 D  = Rw[hi];         // BR

        // conv(2ch) -> relu
        float cv0[4], cv1[4];
#define CONVB(e, B) do { \
        float v0 = fmaf(wc0.x, (B).x, fmaf(wc0.y, (B).y, fmaf(wc0.z, (B).z, fmaf(wc0.w, (B).w, bc.x)))); \
        float v1 = fmaf(wc1.x, (B).x, fmaf(wc1.y, (B).y, fmaf(wc1.z, (B).z, fmaf(wc1.w, (B).w, bc.y)))); \
        cv0[e] = fmaxf(v0, 0.0f); cv1[e] = fmaxf(v1, 0.0f); } while (0)
        CONVB(0, A); CONVB(1, Bq); CONVB(2, C); CONVB(3, D);
#undef CONVB

        // argmax (first-max semantics: strict >)
        int am0 = 0, am1 = 0;
        float mv0 = cv0[0], mv1 = cv1[0];
#pragma unroll
        for (int e = 1; e < 4; e++) {
            if (cv0[e] > mv0) { mv0 = cv0[e]; am0 = e; }
            if (cv1[e] > mv1) { mv1 = cv1[e]; am1 = e; }
        }

        // dense + relu
        const float z0 = fmaxf(fmaf(mv0, wb.x, fmaf(mv1, wb.y, bb.x)), 0.0f);
        const float z1 = fmaxf(fmaf(mv0, wb.z, fmaf(mv1, wb.w, bb.y)), 0.0f);
        const float zz1 = (am0 == am1) ? z1 : 0.0f;

        // row+col validity folded into scale
        const float hf = ((unsigned)pr <= 510u) ? hfk : 0.0f;
        const float hfc = fmaf(thc, hf, hf);

        // 8 live tanh, pre-scaled: value = hf*(tanh+1)
        float th0s[4], th1s[4];
#pragma unroll
        for (int pq = 0; pq < 4; pq++) {
            th0s[pq] = fmaf(tanhf_fast(fmaf(z0, wd0h[pq], fmaf(zz1, wd1h[pq], bdh))), hf, hf);
            th1s[pq] = fmaf(tanhf_fast(fmaf(z1, wd1h[pq], bdh)), hf, hf);
        }

        // quadrant groups via selects
        float4 grp[4];
#pragma unroll
        for (int g = 0; g < 4; g++) {
            const bool p0 = (am0 == g);
            const bool p1 = (am1 == g);
            grp[g].x = p0 ? th0s[0] : (p1 ? th1s[0] : hfc);
            grp[g].y = p0 ? th0s[1] : (p1 ? th1s[1] : hfc);
            grp[g].z = p0 ? th0s[2] : (p1 ? th1s[2] : hfc);
            grp[g].w = p0 ? th0s[3] : (p1 ? th1s[3] : hfc);
        }
        const float4 gTL = grp[0];
        const float4 gTR = grp[1];
        const float4 gBL = grp[2];
        const float4 gBR = grp[3];

        // horizontal routing: right-neighbor lane's TL and BL
        float4 nTL, nBL;
        nTL.x = __shfl_down_sync(0xffffffffu, gTL.x, 1);
        nTL.y = __shfl_down_sync(0xffffffffu, gTL.y, 1);
        nTL.z = __shfl_down_sync(0xffffffffu, gTL.z, 1);
        nTL.w = __shfl_down_sync(0xffffffffu, gTL.w, 1);
        nBL.x = __shfl_down_sync(0xffffffffu, gBL.x, 1);
        nBL.y = __shfl_down_sync(0xffffffffu, gBL.y, 1);
        nBL.z = __shfl_down_sync(0xffffffffu, gBL.z, 1);
        nBL.w = __shfl_down_sync(0xffffffffu, gBL.w, 1);

        // emit cell row A = pr (skip warm-up i=0); vertical routing via 'carry'
        if (i > 0) {
            if (cell_ok) {
                const float rcp = (pr == 0 || pr == 511) ? rcp_edge : rcp_mid;
                const float pix00 = (carry.x + gTR.x) + nTL.x;
                const float pix01 = (carry.y + gTR.y) + nTL.y;
                const float pix10 = (carry.z + gTR.z) + nTL.z;
                const float pix11 = (carry.w + gTR.w) + nTL.w;
                *(float2*)(op)      = make_float2(pix00 * rcp, pix01 * rcp);
                *(float2*)(op + IW) = make_float2(pix10 * rcp, pix11 * rcp);
            }
            op += 2 * IW;
        }

        // new vertical carry for cell row pr+1
        carry.x = gBR.x + nBL.x;
        carry.y = gBR.y + nBL.y;
        carry.z = gBR.z + nBL.z;
        carry.w = gBR.w + nBL.w;

        // slide window: slot lo now holds block row pr+2
        Ow[lo] = tO;
        Rw[lo] = tR;
    }
}

extern "C" void kernel_launch(void* const* d_in, const int* in_sizes, int n_in,
                              void* d_out, int out_size) {
    const float* img    = (const float*)d_in[0];
    const float* w_conv = (const float*)d_in[1];
    const float* b_conv = (const float*)d_in[2];
    const float* W_b    = (const float*)d_in[3];
    const float* b_b    = (const float*)d_in[4];
    const float* W_d    = (const float*)d_in[5];
    const float* b_d    = (const float*)d_in[6];
    float* out = (float*)d_out;

    // 8 imgs x 32 segments x 17 col-warps = 4352 warps / 4 per block
    dim3 grid(8 * NSEG * COLW / WPB);   // 1088 blocks
    dim3 block(128);
    ae_kernel<<<grid, block>>>(img, w_conv, b_conv, W_b, b_b, W_d, b_d, out);
}

// round 13
// speedup vs baseline: 1.4067x; 1.0031x over previous
#include <cuda_runtime.h>

#define IH 1024
#define IW 1024
#define IMG_PIX (IH * IW)
#define NSEG 32            // row segments per image (16 cell rows each)
#define SEG_ROWS 16
#define COLW 17            // col-warps per row strip (31 owned cell cols each)
#define WPB 4              // warps per block

__device__ __forceinline__ float tanhf_fast(float x) {
    float y; asm("tanh.approx.f32 %0, %1;" : "=f"(y) : "f"(x)); return y;
}

__global__ __launch_bounds__(128, 8)
void ae_kernel(const float* __restrict__ img,
               const float* __restrict__ w_conv,  // (2,1,2,2)
               const float* __restrict__ b_conv,  // (2,)
               const float* __restrict__ W_b,     // (2,2)
               const float* __restrict__ b_b,     // (2,)
               const float* __restrict__ W_d,     // (2,1,2,2)
               const float* __restrict__ b_d,     // (1,)
               float* __restrict__ out)
{
    const int lane = threadIdx.x & 31;
    const int gw   = blockIdx.x * WPB + (threadIdx.x >> 5);
    const int c    = gw % COLW;          // col-warp
    const int t    = gw / COLW;
    const int s    = t & (NSEG - 1);     // row segment
    const int im   = t >> 5;             // image

    // ---- tiny weights -> registers (uniform) ----
    const float4 wc0 = __ldg((const float4*)w_conv);
    const float4 wc1 = __ldg((const float4*)(w_conv + 4));
    const float2 bc  = __ldg((const float2*)b_conv);
    const float4 wb  = __ldg((const float4*)W_b);
    const float2 bb  = __ldg((const float2*)b_b);
    float wd0h[4], wd1h[4];
    {
        const float4 t0 = __ldg((const float4*)W_d);
        const float4 t1 = __ldg((const float4*)(W_d + 4));
        wd0h[0]=t0.x*0.5f; wd0h[1]=t0.y*0.5f; wd0h[2]=t0.z*0.5f; wd0h[3]=t0.w*0.5f;
        wd1h[0]=t1.x*0.5f; wd1h[1]=t1.y*0.5f; wd1h[2]=t1.z*0.5f; wd1h[3]=t1.w*0.5f;
    }
    const float bdh = __ldg(b_d) * 0.5f;
    const float thc = tanhf_fast(bdh);

    // ---- lane geometry (invariant) ----
    const int kc = 31 * c + lane - 1;     // own patch col (may be -1 or >510)
    const int CB = kc + 1;                // own cell col
    const float hfk = ((unsigned)kc <= 510u) ? 0.5f : 0.0f;
    const int colf = (int)((unsigned)kc <= 510u) + (int)((unsigned)CB <= 510u);
    const float rcp_mid  = (colf == 2) ? 0.25f : 0.5f;   // interior cell rows
    const float rcp_edge = (colf == 2) ? 0.5f  : 1.0f;   // cell rows 0 and 511
    const bool cell_ok = (lane < 31) && (CB <= 511);

    // clamped column bases (OOB patches have hf=0; clamped garbage never escapes)
    const int gcL = 2 * kc;
    const int colO = min(max(gcL, 0), 1022);       // own block cols
    const int colR = min(max(gcL + 2, 0), 1022);   // right block cols

    const float* ibase = img + (size_t)im * IMG_PIX;
    float* op = out + (size_t)im * IMG_PIX + (size_t)(32 * s) * IW + 2 * CB;

    // load block row b (pixel rows clamp(2b), +1), unconditional LDG.64 x4
    auto LOADBR = [&](int b, float4& O, float4& R) {
        const int ro = min(max(2 * b, 0), 1022);
        const float* p = ibase + (long long)ro * IW;
        const float2 ot  = *(const float2*)(p + colO);
        const float2 rt  = *(const float2*)(p + colR);
        const float2 obm = *(const float2*)(p + IW + colO);
        const float2 rb  = *(const float2*)(p + IW + colR);
        O = make_float4(ot.x, ot.y, obm.x, obm.y);
        R = make_float4(rt.x, rt.y, rb.x, rb.y);
    };

#define CONVB(e, B) do { \
        float v0 = fmaf(wc0.x, (B).x, fmaf(wc0.y, (B).y, fmaf(wc0.z, (B).z, fmaf(wc0.w, (B).w, bc.x)))); \
        float v1 = fmaf(wc1.x, (B).x, fmaf(wc1.y, (B).y, fmaf(wc1.z, (B).z, fmaf(wc1.w, (B).w, bc.y)))); \
        cv0[e] = fmaxf(v0, 0.0f); cv1[e] = fmaxf(v1, 0.0f); } while (0)

    // shared patch pipeline: conv inputs in cv -> z0,z1,am0,am1, tanh sets
#define PATCH_CORE(PR)                                                        \
        int am0 = 0, am1 = 0;                                                 \
        float mv0 = cv0[0], mv1 = cv1[0];                                     \
        _Pragma("unroll")                                                     \
        for (int e = 1; e < 4; e++) {                                         \
            if (cv0[e] > mv0) { mv0 = cv0[e]; am0 = e; }                      \
            if (cv1[e] > mv1) { mv1 = cv1[e]; am1 = e; }                      \
        }                                                                     \
        const float z0 = fmaxf(fmaf(mv0, wb.x, fmaf(mv1, wb.y, bb.x)), 0.0f); \
        const float z1 = fmaxf(fmaf(mv0, wb.z, fmaf(mv1, wb.w, bb.y)), 0.0f); \
        const float zz1 = (am0 == am1) ? z1 : 0.0f;                           \
        const float hf = ((unsigned)(PR) <= 510u) ? hfk : 0.0f;               \
        const float hfc = fmaf(thc, hf, hf);                                  \
        float th0s[4], th1s[4];                                               \
        _Pragma("unroll")                                                     \
        for (int pq = 0; pq < 4; pq++) {                                      \
            th0s[pq] = fmaf(tanhf_fast(fmaf(z0, wd0h[pq], fmaf(zz1, wd1h[pq], bdh))), hf, hf); \
            th1s[pq] = fmaf(tanhf_fast(fmaf(z1, wd1h[pq], bdh)), hf, hf);     \
        }

#define GRP(dst, g) do {                                                      \
        const bool p0 = (am0 == (g));                                         \
        const bool p1 = (am1 == (g));                                         \
        (dst).x = p0 ? th0s[0] : (p1 ? th1s[0] : hfc);                        \
        (dst).y = p0 ? th0s[1] : (p1 ? th1s[1] : hfc);                        \
        (dst).z = p0 ? th0s[2] : (p1 ? th1s[2] : hfc);                        \
        (dst).w = p0 ? th0s[3] : (p1 ? th1s[3] : hfc); } while (0)

    // ---- window init: Ow[1]=block row pr0, Ow[0]=block row pr0+1 ----
    float4 Ow[2], Rw[2];
    const int pr0 = 16 * s - 1;           // warm-up patch row
    LOADBR(pr0,     Ow[1], Rw[1]);
    LOADBR(pr0 + 1, Ow[0], Rw[0]);

    float4 carry;
    {   // ---- peeled warm-up (i=0): only BL/BR groups needed ----
        float cv0[4], cv1[4];
        CONVB(0, Ow[1]); CONVB(1, Rw[1]); CONVB(2, Ow[0]); CONVB(3, Rw[0]);
        LOADBR(pr0 + 2, Ow[1], Rw[1]);    // refill slot lo=1 with row pr0+2
        PATCH_CORE(pr0)
        float4 gBL, gBR;
        GRP(gBL, 2);
        GRP(gBR, 3);
        carry.x = gBR.x + __shfl_down_sync(0xffffffffu, gBL.x, 1);
        carry.y = gBR.y + __shfl_down_sync(0xffffffffu, gBL.y, 1);
        carry.z = gBR.z + __shfl_down_sync(0xffffffffu, gBL.z, 1);
        carry.w = gBR.w + __shfl_down_sync(0xffffffffu, gBL.w, 1);
    }

#pragma unroll 2
    for (int i = 1; i <= SEG_ROWS; i++) {
        const int pr = pr0 + i;           // patch row (== emitted cell row)
        const int lo = (i + 1) & 1;       // slot of block row pr
        const int hi = i & 1;             // slot of block row pr+1

        float cv0[4], cv1[4];
        CONVB(0, Ow[lo]); CONVB(1, Rw[lo]); CONVB(2, Ow[hi]); CONVB(3, Rw[hi]);
        LOADBR(pr + 2, Ow[lo], Rw[lo]);   // refill consumed slot (hidden until next iter)

        PATCH_CORE(pr)

        float4 gTL, gTR, gBL, gBR;
        GRP(gTL, 0); GRP(gTR, 1); GRP(gBL, 2); GRP(gBR, 3);

        // horizontal routing from lane+1
        float4 nTL, nBL;
        nTL.x = __shfl_down_sync(0xffffffffu, gTL.x, 1);
        nTL.y = __shfl_down_sync(0xffffffffu, gTL.y, 1);
        nTL.z = __shfl_down_sync(0xffffffffu, gTL.z, 1);
        nTL.w = __shfl_down_sync(0xffffffffu, gTL.w, 1);
        nBL.x = __shfl_down_sync(0xffffffffu, gBL.x, 1);
        nBL.y = __shfl_down_sync(0xffffffffu, gBL.y, 1);
        nBL.z = __shfl_down_sync(0xffffffffu, gBL.z, 1);
        nBL.w = __shfl_down_sync(0xffffffffu, gBL.w, 1);

        // emit cell row pr
        if (cell_ok) {
            const float rcp = (pr == 0 || pr == 511) ? rcp_edge : rcp_mid;
            const float pix00 = (carry.x + gTR.x) + nTL.x;
            const float pix01 = (carry.y + gTR.y) + nTL.y;
            const float pix10 = (carry.z + gTR.z) + nTL.z;
            const float pix11 = (carry.w + gTR.w) + nTL.w;
            *(float2*)(op)      = make_float2(pix00 * rcp, pix01 * rcp);
            *(float2*)(op + IW) = make_float2(pix10 * rcp, pix11 * rcp);
        }
        op += 2 * IW;

        // vertical carry for next cell row
        carry.x = gBR.x + nBL.x;
        carry.y = gBR.y + nBL.y;
        carry.z = gBR.z + nBL.z;
        carry.w = gBR.w + nBL.w;
    }
#undef GRP
#undef PATCH_CORE
#undef CONVB
}

extern "C" void kernel_launch(void* const* d_in, const int* in_sizes, int n_in,
                              void* d_out, int out_size) {
    const float* img    = (const float*)d_in[0];
    const float* w_conv = (const float*)d_in[1];
    const float* b_conv = (const float*)d_in[2];
    const float* W_b    = (const float*)d_in[3];
    const float* b_b    = (const float*)d_in[4];
    const float* W_d    = (const float*)d_in[5];
    const float* b_d    = (const float*)d_in[6];
    float* out = (float*)d_out;

    // 8 imgs x 32 segments x 17 col-warps = 4352 warps / 4 per block
    dim3 grid(8 * NSEG * COLW / WPB);   // 1088 blocks
    dim3 block(128);
    ae_kernel<<<grid, block>>>(img, w_conv, b_conv, W_b, b_b, W_d, b_d, out);
}